// round 2
// baseline (speedup 1.0000x reference)
#include <cuda_runtime.h>
#include <cuda_bf16.h>
#include <cstdint>

// Problem shape (fixed by the reference):
//   token_reprs: [B=32, L=512, H=768] float32
//   pos_idx:     [B=32, E=32, M=8, S=4] int32 (JAX downcasts int64 w/o x64)
// Outputs (concatenated f32 in d_out):
//   entity_reprs  [B, E, H]     = 786432   @ offset 0
//   mentions_reprs[B, E, M, H]  = 6291456  @ offset 786432
//   mentions_mask [B, E, M]     = 8192     @ offset 7077888

#define B_ 32
#define L_ 512
#define H_ 768
#define E_ 32
#define M_ 8
#define S_ 4
#define HV (H_ / 4)          // 192 float4 per row

__global__ __launch_bounds__(HV, 8)
void entity_repr_kernel(const float* __restrict__ tok,
                        const int* __restrict__ pos,
                        float* __restrict__ ent,
                        float* __restrict__ men,
                        float* __restrict__ mask)
{
    const int be = blockIdx.x;          // 0 .. B*E-1
    const int b  = be >> 5;             // E_ == 32

    __shared__ int sidx[M_ * S_];
    if (threadIdx.x < M_ * S_) {
        sidx[threadIdx.x] = pos[(size_t)be * (M_ * S_) + threadIdx.x];
    }
    __syncthreads();

    const int t = threadIdx.x;          // float4 column index, 0..191
    const float4* __restrict__ tokb =
        reinterpret_cast<const float4*>(tok) + (size_t)b * L_ * HV;

    float4* __restrict__ men4 =
        reinterpret_cast<float4*>(men) + ((size_t)be * M_) * HV;
    float4* __restrict__ ent4 =
        reinterpret_cast<float4*>(ent) + (size_t)be * HV;

    float ex = 0.f, ey = 0.f, ez = 0.f, ew = 0.f;

    #pragma unroll
    for (int m = 0; m < M_; m++) {
        // 4 independent gathered loads -> MLP=4 per mention
        const float4 v0 = tokb[(size_t)sidx[m * S_ + 0] * HV + t];
        const float4 v1 = tokb[(size_t)sidx[m * S_ + 1] * HV + t];
        const float4 v2 = tokb[(size_t)sidx[m * S_ + 2] * HV + t];
        const float4 v3 = tokb[(size_t)sidx[m * S_ + 3] * HV + t];

        float4 r;
        r.x = (v0.x + v1.x + v2.x + v3.x) * 0.25f;
        r.y = (v0.y + v1.y + v2.y + v3.y) * 0.25f;
        r.z = (v0.z + v1.z + v2.z + v3.z) * 0.25f;
        r.w = (v0.w + v1.w + v2.w + v3.w) * 0.25f;

        men4[(size_t)m * HV + t] = r;

        ex += r.x; ey += r.y; ez += r.z; ew += r.w;
    }

    float4 er;
    er.x = ex * 0.125f; er.y = ey * 0.125f;
    er.z = ez * 0.125f; er.w = ew * 0.125f;
    ent4[t] = er;

    if (t < M_) {
        mask[(size_t)be * M_ + t] = 1.0f;
    }
}

extern "C" void kernel_launch(void* const* d_in, const int* in_sizes, int n_in,
                              void* d_out, int out_size)
{
    const float* tok = (const float*)d_in[0];
    const int*   pos = (const int*)d_in[1];

    float* out = (float*)d_out;
    float* ent  = out;                                  // 786432
    float* men  = out + (size_t)B_ * E_ * H_;           // +786432
    float* mask = men + (size_t)B_ * E_ * M_ * H_;      // +6291456

    entity_repr_kernel<<<B_ * E_, HV>>>(tok, pos, ent, men, mask);
}